// round 1
// baseline (speedup 1.0000x reference)
#include <cuda_runtime.h>
#include <math.h>

#define B_ROWS 8192
#define N_IN   12288
#define H0     256
#define H1     32
#define H2     32

// Scratch: transposed feature weights [N_IN][H0] (12.6 MB, L2-resident)
__device__ float g_ftwT[N_IN * H0];
__device__ int   g_side_mode; // 0=int32, 1=float32, 2=byte

// ---------------------------------------------------------------------------
// Tiled transpose: ft_w [H0, N_IN] row-major -> g_ftwT [N_IN, H0]
// ---------------------------------------------------------------------------
__global__ void transpose_kernel(const float* __restrict__ ft_w) {
    __shared__ float tile[32][33];
    int n0 = blockIdx.x * 32;
    int h0 = blockIdx.y * 32;
    int tx = threadIdx.x;          // 0..31
    int ty = threadIdx.y;          // 0..7
    #pragma unroll
    for (int r = ty; r < 32; r += 8)
        tile[r][tx] = ft_w[(size_t)(h0 + r) * N_IN + n0 + tx];
    __syncthreads();
    #pragma unroll
    for (int r = ty; r < 32; r += 8)
        g_ftwT[(size_t)(n0 + r) * H0 + h0 + tx] = tile[tx][r];
}

// ---------------------------------------------------------------------------
// Detect storage layout of the bool 'side' array. Scans only the first
// 2048 32-bit words, which is in-bounds for byte, int32, or float32 storage.
//   int32  : words are 0 or 1
//   float32: words are 0 or 0x3F800000
//   bytes  : words are packings of 0x00/0x01 -> values like 0x00010001
// ---------------------------------------------------------------------------
__global__ void detect_side_kernel(const unsigned int* __restrict__ w) {
    __shared__ int cnt_other, cnt_float;
    if (threadIdx.x == 0) { cnt_other = 0; cnt_float = 0; }
    __syncthreads();
    for (int i = threadIdx.x; i < 2048; i += blockDim.x) {
        unsigned int v = w[i];
        if (v == 0x3F800000u)      atomicAdd(&cnt_float, 1);
        else if (v != 0u && v != 1u) atomicAdd(&cnt_other, 1);
    }
    __syncthreads();
    if (threadIdx.x == 0)
        g_side_mode = (cnt_other > 0) ? 2 : (cnt_float > 0 ? 1 : 0);
}

// ---------------------------------------------------------------------------
// Main fused NNUE kernel: one CTA (256 threads) per batch row.
//   phase 1: scan white/black feature rows (float4), collect nonzero indices
//            in shared, gather-accumulate ft_wT rows. Thread t owns acc[h=t].
//   phase 2: side-select concat -> clip -> l1 -> clip -> l2 -> clip -> l3
//            -> *300 -> sigmoid(/200)
// ---------------------------------------------------------------------------
__global__ __launch_bounds__(256, 8) void nnue_kernel(
    const float* __restrict__ wf, const float* __restrict__ bf,
    const void*  __restrict__ side,
    const float* __restrict__ ft_b,
    const float* __restrict__ l1w, const float* __restrict__ l1b,
    const float* __restrict__ l2w, const float* __restrict__ l2b,
    const float* __restrict__ l3w, const float* __restrict__ l3b,
    float* __restrict__ out)
{
    __shared__ int   s_idx[4096];
    __shared__ int   s_cnt;
    __shared__ float s_acc[2 * H0];
    __shared__ float s_o1[H1];

    const int row = blockIdx.x;
    const int t   = threadIdx.x;

    float accv[2];

    #pragma unroll
    for (int sdx = 0; sdx < 2; sdx++) {
        const float4* rp = (const float4*)((sdx == 0 ? wf : bf)
                              + (size_t)row * N_IN);
        float acc  = ft_b[t];
        float acc2 = 0.0f;

        // 3 chunks of 4096 floats (1024 float4) each
        for (int chunk = 0; chunk < 3; chunk++) {
            if (t == 0) s_cnt = 0;
            __syncthreads();

            int base4 = chunk * 1024;
            #pragma unroll
            for (int it = 0; it < 4; it++) {
                int i4 = base4 + it * 256 + t;
                float4 v = rp[i4];
                int fi = i4 * 4;
                if (v.x != 0.0f) s_idx[atomicAdd(&s_cnt, 1)] = fi;
                if (v.y != 0.0f) s_idx[atomicAdd(&s_cnt, 1)] = fi + 1;
                if (v.z != 0.0f) s_idx[atomicAdd(&s_cnt, 1)] = fi + 2;
                if (v.w != 0.0f) s_idx[atomicAdd(&s_cnt, 1)] = fi + 3;
            }
            __syncthreads();

            int cnt = s_cnt;
            int k = 0;
            for (; k + 2 <= cnt; k += 2) {
                acc  += g_ftwT[(size_t)s_idx[k]     * H0 + t];
                acc2 += g_ftwT[(size_t)s_idx[k + 1] * H0 + t];
            }
            if (k < cnt)
                acc += g_ftwT[(size_t)s_idx[k] * H0 + t];
            __syncthreads();   // protect s_idx/s_cnt for next chunk
        }
        accv[sdx] = acc + acc2;
    }

    // side flag, robust to storage layout
    int mode = g_side_mode;
    bool sflag;
    if (mode == 0)      sflag = ((const int*)side)[row] != 0;
    else if (mode == 1) sflag = ((const float*)side)[row] != 0.0f;
    else                sflag = ((const unsigned char*)side)[row] != 0;

    float cw = fminf(fmaxf(accv[0], 0.0f), 1.0f);
    float cb = fminf(fmaxf(accv[1], 0.0f), 1.0f);
    if (sflag) { s_acc[t] = cw; s_acc[t + H0] = cb; }
    else       { s_acc[t] = cb; s_acc[t + H0] = cw; }
    __syncthreads();

    // layer 1: 32 outputs x 512 inputs. 8 threads per output (same warp).
    {
        int j = t >> 3;      // output index 0..31
        int g = t & 7;       // lane-in-group
        float sum = 0.0f;
        #pragma unroll 16
        for (int k = 0; k < 64; k++)
            sum += l1w[j * 512 + g + k * 8] * s_acc[g + k * 8];
        sum += __shfl_down_sync(0xFFFFFFFFu, sum, 4);
        sum += __shfl_down_sync(0xFFFFFFFFu, sum, 2);
        sum += __shfl_down_sync(0xFFFFFFFFu, sum, 1);
        if (g == 0)
            s_o1[j] = fminf(fmaxf(sum + l1b[j], 0.0f), 1.0f);
    }
    __syncthreads();

    // layers 2 + 3 on warp 0
    if (t < 32) {
        float s2 = l2b[t];
        #pragma unroll
        for (int k = 0; k < 32; k++)
            s2 += l2w[t * 32 + k] * s_o1[k];
        float o2 = fminf(fmaxf(s2, 0.0f), 1.0f);
        float v = o2 * l3w[t];
        #pragma unroll
        for (int off = 16; off > 0; off >>= 1)
            v += __shfl_down_sync(0xFFFFFFFFu, v, off);
        if (t == 0) {
            float o3 = (v + l3b[0]) * 300.0f;
            out[row] = 1.0f / (1.0f + expf(-o3 / 200.0f));
        }
    }
}

// ---------------------------------------------------------------------------
extern "C" void kernel_launch(void* const* d_in, const int* in_sizes, int n_in,
                              void* d_out, int out_size) {
    const float* wf   = (const float*)d_in[0];
    const float* bf   = (const float*)d_in[1];
    const void*  side = d_in[2];
    const float* ft_w = (const float*)d_in[3];
    const float* ft_b = (const float*)d_in[4];
    const float* l1w  = (const float*)d_in[5];
    const float* l1b  = (const float*)d_in[6];
    const float* l2w  = (const float*)d_in[7];
    const float* l2b  = (const float*)d_in[8];
    const float* l3w  = (const float*)d_in[9];
    const float* l3b  = (const float*)d_in[10];

    transpose_kernel<<<dim3(N_IN / 32, H0 / 32), dim3(32, 8)>>>(ft_w);
    detect_side_kernel<<<1, 256>>>((const unsigned int*)side);
    nnue_kernel<<<B_ROWS, 256>>>(wf, bf, side, ft_b,
                                 l1w, l1b, l2w, l2b, l3w, l3b,
                                 (float*)d_out);
}